// round 1
// baseline (speedup 1.0000x reference)
#include <cuda_runtime.h>
#include <cuda_bf16.h>
#include <math.h>

// Problem constants (sized for this dataset)
#define NMAX 100000
#define EMAX 1600000
#define DEMB 64

// Scratch (static device globals — no allocation)
__device__ float g_h[NMAX * DEMB];      // node features
__device__ float g_hw[NMAX * DEMB];     // transformed features h @ W
__device__ float g_acc[NMAX * DEMB];    // scatter accumulator
__device__ float g_norm[EMAX];          // per-edge normalization
__device__ float g_dis[NMAX];           // deg -> rsqrt(deg)
__device__ float g_selfnorm[NMAX];      // dis^2 (self-loop norm)

// ---------------- degree / norm precompute ----------------

__global__ void k_init_deg(int n) {
    int i = blockIdx.x * blockDim.x + threadIdx.x;
    if (i < n) g_dis[i] = 1.0f;  // self-loop weight
}

__global__ void k_deg_accum(const int* __restrict__ ei,
                            const float* __restrict__ ew, int e) {
    int i = blockIdx.x * blockDim.x + threadIdx.x;
    if (i < e) atomicAdd(&g_dis[ei[e + i]], ew[i]);  // col = target
}

__global__ void k_dis(int n) {
    int i = blockIdx.x * blockDim.x + threadIdx.x;
    if (i < n) {
        float d = g_dis[i];
        float r = (d > 0.0f) ? rsqrtf(d) : 0.0f;
        g_dis[i] = r;
        g_selfnorm[i] = r * r;
    }
}

__global__ void k_edge_norm(const int* __restrict__ ei,
                            const float* __restrict__ ew, int e) {
    int i = blockIdx.x * blockDim.x + threadIdx.x;
    if (i < e) {
        int r = ei[i];
        int c = ei[e + i];
        g_norm[i] = g_dis[r] * ew[i] * g_dis[c];
    }
}

// ---------------- encoder MLP: h = relu(x@W1+b1)@W2+b2 ----------------

__global__ void k_encoder(const float* __restrict__ x,
                          const float* __restrict__ w1,
                          const float* __restrict__ b1,
                          const float* __restrict__ w2,
                          const float* __restrict__ b2, int n) {
    __shared__ float4 W2s[DEMB * 16];   // [64][16 float4]
    __shared__ float  W1s[2 * DEMB];
    __shared__ float  B1s[DEMB];
    __shared__ float4 B2s[16];
    for (int i = threadIdx.x; i < DEMB * 16; i += blockDim.x)
        W2s[i] = reinterpret_cast<const float4*>(w2)[i];
    for (int i = threadIdx.x; i < 2 * DEMB; i += blockDim.x) W1s[i] = w1[i];
    for (int i = threadIdx.x; i < DEMB; i += blockDim.x) B1s[i] = b1[i];
    for (int i = threadIdx.x; i < 16; i += blockDim.x)
        B2s[i] = reinterpret_cast<const float4*>(b2)[i];
    __syncthreads();

    int nd = blockIdx.x * blockDim.x + threadIdx.x;
    if (nd >= n) return;
    float x0 = x[nd * 2 + 0], x1 = x[nd * 2 + 1];

    float h1[DEMB];
#pragma unroll
    for (int j = 0; j < DEMB; j++)
        h1[j] = fmaxf(fmaf(x0, W1s[j], fmaf(x1, W1s[DEMB + j], B1s[j])), 0.0f);

    float4* out = reinterpret_cast<float4*>(g_h + nd * DEMB);
#pragma unroll
    for (int j4 = 0; j4 < 16; j4++) {
        float4 a = B2s[j4];
#pragma unroll
        for (int k = 0; k < DEMB; k++) {
            float4 w = W2s[k * 16 + j4];
            a.x = fmaf(h1[k], w.x, a.x);
            a.y = fmaf(h1[k], w.y, a.y);
            a.z = fmaf(h1[k], w.z, a.z);
            a.w = fmaf(h1[k], w.w, a.w);
        }
        out[j4] = a;
    }
}

// ---------------- GCN transform: hw = h@W[l]; acc = hw*selfnorm ----------------

__global__ void k_gemm_gcn(const float* __restrict__ gcn_w, int l, int n) {
    __shared__ float4 Ws[DEMB * 16];
    const float4* Wg = reinterpret_cast<const float4*>(gcn_w + (size_t)l * DEMB * DEMB);
    for (int i = threadIdx.x; i < DEMB * 16; i += blockDim.x) Ws[i] = Wg[i];
    __syncthreads();

    int nd = blockIdx.x * blockDim.x + threadIdx.x;
    if (nd >= n) return;

    float h[DEMB];
    const float4* hv = reinterpret_cast<const float4*>(g_h + nd * DEMB);
#pragma unroll
    for (int i = 0; i < 16; i++) {
        float4 t = hv[i];
        h[i * 4 + 0] = t.x; h[i * 4 + 1] = t.y;
        h[i * 4 + 2] = t.z; h[i * 4 + 3] = t.w;
    }
    float sn = g_selfnorm[nd];
    float4* hwv = reinterpret_cast<float4*>(g_hw + nd * DEMB);
    float4* accv = reinterpret_cast<float4*>(g_acc + nd * DEMB);

#pragma unroll
    for (int j4 = 0; j4 < 16; j4++) {
        float4 a = make_float4(0.f, 0.f, 0.f, 0.f);
#pragma unroll
        for (int k = 0; k < DEMB; k++) {
            float4 w = Ws[k * 16 + j4];
            a.x = fmaf(h[k], w.x, a.x);
            a.y = fmaf(h[k], w.y, a.y);
            a.z = fmaf(h[k], w.z, a.z);
            a.w = fmaf(h[k], w.w, a.w);
        }
        hwv[j4] = a;
        accv[j4] = make_float4(a.x * sn, a.y * sn, a.z * sn, a.w * sn);
    }
}

// ---------------- edge scatter: acc[col] += hw[row] * norm ----------------
// 16 threads per edge, each handles one float4 chunk (coalesced 256B/edge).

__global__ void k_scatter(const int* __restrict__ ei, int e) {
    int idx = blockIdx.x * blockDim.x + threadIdx.x;
    if (idx >= e * 16) return;
    int ed = idx >> 4;
    int c = idx & 15;
    int r = ei[ed];
    int col = ei[e + ed];
    float nm = g_norm[ed];
    float4 v = reinterpret_cast<const float4*>(g_hw)[r * 16 + c];
    float4 m = make_float4(v.x * nm, v.y * nm, v.z * nm, v.w * nm);
    atomicAdd(reinterpret_cast<float4*>(g_acc) + (size_t)col * 16 + c, m);
}

// ---------------- bias + relu: h = relu(acc + b[l]) ----------------

__global__ void k_bias_relu(const float* __restrict__ gcn_b, int l, int n) {
    int idx = blockIdx.x * blockDim.x + threadIdx.x;
    if (idx >= n * DEMB) return;
    int j = idx & (DEMB - 1);
    float v = g_acc[idx] + __ldg(&gcn_b[l * DEMB + j]);
    g_h[idx] = fmaxf(v, 0.0f);
}

// ---------------- decoder + softmax + residual ----------------

__global__ void k_decoder(const float* __restrict__ x,
                          const float* __restrict__ w1,
                          const float* __restrict__ b1,
                          const float* __restrict__ w2,
                          const float* __restrict__ b2,
                          float* __restrict__ out, int n) {
    __shared__ float4 W1s[DEMB * 16];
    __shared__ float4 B1s[16];
    __shared__ float  W2s[DEMB * 2];
    __shared__ float  B2s[2];
    for (int i = threadIdx.x; i < DEMB * 16; i += blockDim.x)
        W1s[i] = reinterpret_cast<const float4*>(w1)[i];
    for (int i = threadIdx.x; i < 16; i += blockDim.x)
        B1s[i] = reinterpret_cast<const float4*>(b1)[i];
    for (int i = threadIdx.x; i < DEMB * 2; i += blockDim.x) W2s[i] = w2[i];
    for (int i = threadIdx.x; i < 2; i += blockDim.x) B2s[i] = b2[i];
    __syncthreads();

    int nd = blockIdx.x * blockDim.x + threadIdx.x;
    if (nd >= n) return;

    float h[DEMB];
    const float4* hv = reinterpret_cast<const float4*>(g_h + nd * DEMB);
#pragma unroll
    for (int i = 0; i < 16; i++) {
        float4 t = hv[i];
        h[i * 4 + 0] = t.x; h[i * 4 + 1] = t.y;
        h[i * 4 + 2] = t.z; h[i * 4 + 3] = t.w;
    }

    float o0 = B2s[0], o1 = B2s[1];
#pragma unroll
    for (int j4 = 0; j4 < 16; j4++) {
        float4 a = B1s[j4];
#pragma unroll
        for (int k = 0; k < DEMB; k++) {
            float4 w = W1s[k * 16 + j4];
            a.x = fmaf(h[k], w.x, a.x);
            a.y = fmaf(h[k], w.y, a.y);
            a.z = fmaf(h[k], w.z, a.z);
            a.w = fmaf(h[k], w.w, a.w);
        }
        a.x = fmaxf(a.x, 0.f); a.y = fmaxf(a.y, 0.f);
        a.z = fmaxf(a.z, 0.f); a.w = fmaxf(a.w, 0.f);
        int j = j4 * 4;
        o0 += a.x * W2s[(j + 0) * 2 + 0] + a.y * W2s[(j + 1) * 2 + 0]
            + a.z * W2s[(j + 2) * 2 + 0] + a.w * W2s[(j + 3) * 2 + 0];
        o1 += a.x * W2s[(j + 0) * 2 + 1] + a.y * W2s[(j + 1) * 2 + 1]
            + a.z * W2s[(j + 2) * 2 + 1] + a.w * W2s[(j + 3) * 2 + 1];
    }

    float mx = fmaxf(o0, o1);
    float e0 = __expf(o0 - mx), e1 = __expf(o1 - mx);
    float inv = 1.0f / (e0 + e1);
    out[nd * 2 + 0] = e0 * inv + 2.0f * x[nd * 2 + 0];
    out[nd * 2 + 1] = e1 * inv;
}

// ---------------- launch ----------------

extern "C" void kernel_launch(void* const* d_in, const int* in_sizes, int n_in,
                              void* d_out, int out_size) {
    const float* x      = (const float*)d_in[0];
    const int*   ei     = (const int*)d_in[1];
    const float* ew     = (const float*)d_in[2];
    const float* enc_w1 = (const float*)d_in[3];
    const float* enc_b1 = (const float*)d_in[4];
    const float* enc_w2 = (const float*)d_in[5];
    const float* enc_b2 = (const float*)d_in[6];
    const float* gcn_w  = (const float*)d_in[7];
    const float* gcn_b  = (const float*)d_in[8];
    const float* dec_w1 = (const float*)d_in[9];
    const float* dec_b1 = (const float*)d_in[10];
    const float* dec_w2 = (const float*)d_in[11];
    const float* dec_b2 = (const float*)d_in[12];
    float* out = (float*)d_out;

    int n = in_sizes[0] / 2;          // N nodes (x is [N,2])
    int e = in_sizes[1] / 2;          // E edges (edge_index is [2,E])
    int L = in_sizes[7] / (DEMB * DEMB);

    const int BT = 256;
    int nb_n  = (n + BT - 1) / BT;
    int nb_e  = (e + BT - 1) / BT;
    int nb_nf = (n * DEMB + BT - 1) / BT;
    int nb_sc = (e * 16 + BT - 1) / BT;

    k_init_deg<<<nb_n, BT>>>(n);
    k_deg_accum<<<nb_e, BT>>>(ei, ew, e);
    k_dis<<<nb_n, BT>>>(n);
    k_edge_norm<<<nb_e, BT>>>(ei, ew, e);

    k_encoder<<<nb_n, BT>>>(x, enc_w1, enc_b1, enc_w2, enc_b2, n);

    for (int l = 0; l < L; l++) {
        k_gemm_gcn<<<nb_n, BT>>>(gcn_w, l, n);
        k_scatter<<<nb_sc, BT>>>(ei, e);
        k_bias_relu<<<nb_nf, BT>>>(gcn_b, l, n);
    }

    k_decoder<<<nb_n, BT>>>(x, dec_w1, dec_b1, dec_w2, dec_b2, out, n);
}

// round 2
// speedup vs baseline: 1.5105x; 1.5105x over previous
#include <cuda_runtime.h>
#include <cuda_bf16.h>
#include <math.h>

#define NMAX 100000
#define EMAX 1600000
#define DEMB 64
#define SCAN_B 1024

// Scratch (static device globals — no allocation)
__device__ float g_h[NMAX * DEMB];       // node features
__device__ float g_hw[NMAX * DEMB];      // transformed features h @ W
__device__ float g_deg[NMAX];            // degree -> dis
__device__ float g_selfnorm[NMAX];       // dis^2
__device__ int   g_cnt[NMAX];            // in-degree histogram
__device__ int   g_off[NMAX + 1];        // CSR offsets (by target)
__device__ int   g_woff[NMAX];           // write cursors for bucket fill
__device__ int   g_bsum[(NMAX + SCAN_B - 1) / SCAN_B + 1];
__device__ int2  g_csr[EMAX];            // {src, float_bits(norm)} sorted by target

// ---------------- degree histogram ----------------

__global__ void k_init(int n) {
    int i = blockIdx.x * blockDim.x + threadIdx.x;
    if (i < n) { g_deg[i] = 1.0f; g_cnt[i] = 0; }  // self-loop weight = 1
}

__global__ void k_hist(const int* __restrict__ ei,
                       const float* __restrict__ ew, int e) {
    int i = blockIdx.x * blockDim.x + threadIdx.x;
    if (i < e) {
        int c = ei[e + i];                 // col = target
        atomicAdd(&g_deg[c], ew[i]);
        atomicAdd(&g_cnt[c], 1);
    }
}

__global__ void k_dis(int n) {
    int i = blockIdx.x * blockDim.x + threadIdx.x;
    if (i < n) {
        float d = g_deg[i];
        float r = (d > 0.0f) ? rsqrtf(d) : 0.0f;
        g_deg[i] = r;                      // reuse as dis
        g_selfnorm[i] = r * r;
    }
}

// ---------------- exclusive scan of g_cnt -> g_off ----------------

__global__ void k_scan1(int n) {
    __shared__ int s[SCAN_B];
    int gid = blockIdx.x * SCAN_B + threadIdx.x;
    int v = (gid < n) ? g_cnt[gid] : 0;
    s[threadIdx.x] = v;
    __syncthreads();
#pragma unroll
    for (int off = 1; off < SCAN_B; off <<= 1) {
        int t = (threadIdx.x >= off) ? s[threadIdx.x - off] : 0;
        __syncthreads();
        s[threadIdx.x] += t;
        __syncthreads();
    }
    if (gid < n) g_off[gid] = s[threadIdx.x] - v;  // exclusive
    if (threadIdx.x == SCAN_B - 1) g_bsum[blockIdx.x] = s[SCAN_B - 1];
}

__global__ void k_scan2(int nb, int n, int e) {
    if (threadIdx.x == 0 && blockIdx.x == 0) {
        int run = 0;
        for (int i = 0; i < nb; i++) {
            int t = g_bsum[i];
            g_bsum[i] = run;
            run += t;
        }
        g_off[n] = e;
    }
}

__global__ void k_scan3(int n) {
    int gid = blockIdx.x * SCAN_B + threadIdx.x;
    if (gid < n) {
        int o = g_off[gid] + g_bsum[blockIdx.x];
        g_off[gid] = o;
        g_woff[gid] = o;
    }
}

// ---------------- bucket fill: edges sorted by target + norm ----------------

__global__ void k_build(const int* __restrict__ ei,
                        const float* __restrict__ ew, int e) {
    int i = blockIdx.x * blockDim.x + threadIdx.x;
    if (i < e) {
        int r = ei[i];
        int c = ei[e + i];
        float nm = g_deg[r] * ew[i] * g_deg[c];  // dis[row]*ew*dis[col]
        int pos = atomicAdd(&g_woff[c], 1);
        g_csr[pos] = make_int2(r, __float_as_int(nm));
    }
}

// ---------------- encoder MLP: h = relu(x@W1+b1)@W2+b2 ----------------

__global__ void k_encoder(const float* __restrict__ x,
                          const float* __restrict__ w1,
                          const float* __restrict__ b1,
                          const float* __restrict__ w2,
                          const float* __restrict__ b2, int n) {
    __shared__ float4 W2s[DEMB * 16];
    __shared__ float  W1s[2 * DEMB];
    __shared__ float  B1s[DEMB];
    __shared__ float4 B2s[16];
    for (int i = threadIdx.x; i < DEMB * 16; i += blockDim.x)
        W2s[i] = reinterpret_cast<const float4*>(w2)[i];
    for (int i = threadIdx.x; i < 2 * DEMB; i += blockDim.x) W1s[i] = w1[i];
    for (int i = threadIdx.x; i < DEMB; i += blockDim.x) B1s[i] = b1[i];
    for (int i = threadIdx.x; i < 16; i += blockDim.x)
        B2s[i] = reinterpret_cast<const float4*>(b2)[i];
    __syncthreads();

    int nd = blockIdx.x * blockDim.x + threadIdx.x;
    if (nd >= n) return;
    float x0 = x[nd * 2 + 0], x1 = x[nd * 2 + 1];

    float h1[DEMB];
#pragma unroll
    for (int j = 0; j < DEMB; j++)
        h1[j] = fmaxf(fmaf(x0, W1s[j], fmaf(x1, W1s[DEMB + j], B1s[j])), 0.0f);

    float4* out = reinterpret_cast<float4*>(g_h + nd * DEMB);
#pragma unroll
    for (int j4 = 0; j4 < 16; j4++) {
        float4 a = B2s[j4];
#pragma unroll
        for (int k = 0; k < DEMB; k++) {
            float4 w = W2s[k * 16 + j4];
            a.x = fmaf(h1[k], w.x, a.x);
            a.y = fmaf(h1[k], w.y, a.y);
            a.z = fmaf(h1[k], w.z, a.z);
            a.w = fmaf(h1[k], w.w, a.w);
        }
        out[j4] = a;
    }
}

// ---------------- GCN transform: hw = h@W[l] ----------------

__global__ void k_gemm_gcn(const float* __restrict__ gcn_w, int l, int n) {
    __shared__ float4 Ws[DEMB * 16];
    const float4* Wg = reinterpret_cast<const float4*>(gcn_w + (size_t)l * DEMB * DEMB);
    for (int i = threadIdx.x; i < DEMB * 16; i += blockDim.x) Ws[i] = Wg[i];
    __syncthreads();

    int nd = blockIdx.x * blockDim.x + threadIdx.x;
    if (nd >= n) return;

    float h[DEMB];
    const float4* hv = reinterpret_cast<const float4*>(g_h + nd * DEMB);
#pragma unroll
    for (int i = 0; i < 16; i++) {
        float4 t = hv[i];
        h[i * 4 + 0] = t.x; h[i * 4 + 1] = t.y;
        h[i * 4 + 2] = t.z; h[i * 4 + 3] = t.w;
    }
    float4* hwv = reinterpret_cast<float4*>(g_hw + nd * DEMB);

#pragma unroll
    for (int j4 = 0; j4 < 16; j4++) {
        float4 a = make_float4(0.f, 0.f, 0.f, 0.f);
#pragma unroll
        for (int k = 0; k < DEMB; k++) {
            float4 w = Ws[k * 16 + j4];
            a.x = fmaf(h[k], w.x, a.x);
            a.y = fmaf(h[k], w.y, a.y);
            a.z = fmaf(h[k], w.z, a.z);
            a.w = fmaf(h[k], w.w, a.w);
        }
        hwv[j4] = a;
    }
}

// ---------------- pull aggregation: h = relu(selfnorm*hw[v] + Σ norm*hw[src] + b) ----------------
// 16 threads per node, each owns one float4 chunk. No atomics.

__global__ void k_aggregate(const float* __restrict__ gcn_b, int l, int n) {
    int idx = blockIdx.x * blockDim.x + threadIdx.x;
    int v = idx >> 4;
    if (v >= n) return;
    int lane = idx & 15;

    int start = g_off[v];
    int end   = g_off[v + 1];
    float sn = g_selfnorm[v];

    const float4* hw = reinterpret_cast<const float4*>(g_hw);
    float4 hv = hw[(size_t)v * 16 + lane];
    float4 acc = make_float4(hv.x * sn, hv.y * sn, hv.z * sn, hv.w * sn);

    for (int j = start; j < end; j++) {
        int2 p = __ldg(&g_csr[j]);
        float nm = __int_as_float(p.y);
        float4 m = hw[(size_t)p.x * 16 + lane];
        acc.x = fmaf(m.x, nm, acc.x);
        acc.y = fmaf(m.y, nm, acc.y);
        acc.z = fmaf(m.z, nm, acc.z);
        acc.w = fmaf(m.w, nm, acc.w);
    }

    float4 b = __ldg(reinterpret_cast<const float4*>(gcn_b + (size_t)l * DEMB) + lane);
    acc.x = fmaxf(acc.x + b.x, 0.0f);
    acc.y = fmaxf(acc.y + b.y, 0.0f);
    acc.z = fmaxf(acc.z + b.z, 0.0f);
    acc.w = fmaxf(acc.w + b.w, 0.0f);
    reinterpret_cast<float4*>(g_h)[(size_t)v * 16 + lane] = acc;
}

// ---------------- decoder + softmax + residual ----------------

__global__ void k_decoder(const float* __restrict__ x,
                          const float* __restrict__ w1,
                          const float* __restrict__ b1,
                          const float* __restrict__ w2,
                          const float* __restrict__ b2,
                          float* __restrict__ out, int n) {
    __shared__ float4 W1s[DEMB * 16];
    __shared__ float4 B1s[16];
    __shared__ float  W2s[DEMB * 2];
    __shared__ float  B2s[2];
    for (int i = threadIdx.x; i < DEMB * 16; i += blockDim.x)
        W1s[i] = reinterpret_cast<const float4*>(w1)[i];
    for (int i = threadIdx.x; i < 16; i += blockDim.x)
        B1s[i] = reinterpret_cast<const float4*>(b1)[i];
    for (int i = threadIdx.x; i < DEMB * 2; i += blockDim.x) W2s[i] = w2[i];
    for (int i = threadIdx.x; i < 2; i += blockDim.x) B2s[i] = b2[i];
    __syncthreads();

    int nd = blockIdx.x * blockDim.x + threadIdx.x;
    if (nd >= n) return;

    float h[DEMB];
    const float4* hv = reinterpret_cast<const float4*>(g_h + nd * DEMB);
#pragma unroll
    for (int i = 0; i < 16; i++) {
        float4 t = hv[i];
        h[i * 4 + 0] = t.x; h[i * 4 + 1] = t.y;
        h[i * 4 + 2] = t.z; h[i * 4 + 3] = t.w;
    }

    float o0 = B2s[0], o1 = B2s[1];
#pragma unroll
    for (int j4 = 0; j4 < 16; j4++) {
        float4 a = B1s[j4];
#pragma unroll
        for (int k = 0; k < DEMB; k++) {
            float4 w = W1s[k * 16 + j4];
            a.x = fmaf(h[k], w.x, a.x);
            a.y = fmaf(h[k], w.y, a.y);
            a.z = fmaf(h[k], w.z, a.z);
            a.w = fmaf(h[k], w.w, a.w);
        }
        a.x = fmaxf(a.x, 0.f); a.y = fmaxf(a.y, 0.f);
        a.z = fmaxf(a.z, 0.f); a.w = fmaxf(a.w, 0.f);
        int j = j4 * 4;
        o0 += a.x * W2s[(j + 0) * 2 + 0] + a.y * W2s[(j + 1) * 2 + 0]
            + a.z * W2s[(j + 2) * 2 + 0] + a.w * W2s[(j + 3) * 2 + 0];
        o1 += a.x * W2s[(j + 0) * 2 + 1] + a.y * W2s[(j + 1) * 2 + 1]
            + a.z * W2s[(j + 2) * 2 + 1] + a.w * W2s[(j + 3) * 2 + 1];
    }

    float mx = fmaxf(o0, o1);
    float e0 = __expf(o0 - mx), e1 = __expf(o1 - mx);
    float inv = 1.0f / (e0 + e1);
    out[nd * 2 + 0] = e0 * inv + 2.0f * x[nd * 2 + 0];
    out[nd * 2 + 1] = e1 * inv;
}

// ---------------- launch ----------------

extern "C" void kernel_launch(void* const* d_in, const int* in_sizes, int n_in,
                              void* d_out, int out_size) {
    const float* x      = (const float*)d_in[0];
    const int*   ei     = (const int*)d_in[1];
    const float* ew     = (const float*)d_in[2];
    const float* enc_w1 = (const float*)d_in[3];
    const float* enc_b1 = (const float*)d_in[4];
    const float* enc_w2 = (const float*)d_in[5];
    const float* enc_b2 = (const float*)d_in[6];
    const float* gcn_w  = (const float*)d_in[7];
    const float* gcn_b  = (const float*)d_in[8];
    const float* dec_w1 = (const float*)d_in[9];
    const float* dec_b1 = (const float*)d_in[10];
    const float* dec_w2 = (const float*)d_in[11];
    const float* dec_b2 = (const float*)d_in[12];
    float* out = (float*)d_out;

    int n = in_sizes[0] / 2;
    int e = in_sizes[1] / 2;
    int L = in_sizes[7] / (DEMB * DEMB);

    const int BT = 256;
    int nb_n  = (n + BT - 1) / BT;
    int nb_e  = (e + BT - 1) / BT;
    int nb_ag = (n * 16 + BT - 1) / BT;
    int nb_sc = (n + SCAN_B - 1) / SCAN_B;

    // CSR build (once per launch)
    k_init<<<nb_n, BT>>>(n);
    k_hist<<<nb_e, BT>>>(ei, ew, e);
    k_dis<<<nb_n, BT>>>(n);
    k_scan1<<<nb_sc, SCAN_B>>>(n);
    k_scan2<<<1, 32>>>(nb_sc, n, e);
    k_scan3<<<nb_sc, SCAN_B>>>(n);
    k_build<<<nb_e, BT>>>(ei, ew, e);

    // encoder
    k_encoder<<<nb_n, BT>>>(x, enc_w1, enc_b1, enc_w2, enc_b2, n);

    // GCN layers: transform then pull-aggregate (bias+relu fused)
    for (int l = 0; l < L; l++) {
        k_gemm_gcn<<<nb_n, BT>>>(gcn_w, l, n);
        k_aggregate<<<nb_ag, BT>>>(gcn_b, l, n);
    }

    // decoder
    k_decoder<<<nb_n, BT>>>(x, dec_w1, dec_b1, dec_w2, dec_b2, out, n);
}